// round 17
// baseline (speedup 1.0000x reference)
#include <cuda_runtime.h>
#include <math.h>

#define B_    32
#define HB_   16   // half batch
#define INC_  10
#define LIN_  16384
#define CH_   20
#define NPOLY 12
#define MM_   6
#define NB_   4
// lengths: l0=16434 -> 16422,16410,16398,16386 (all divisible by 6)

#define BUFN 10520000  // >= 32*20*16434

__device__ float g_xa[BUFN];
__device__ float g_xb[BUFN];
__device__ float g_y1[BUFN];
__device__ float g_y2[BUFN];
__device__ float g_lg[BUFN];

typedef unsigned long long ull;

__device__ __forceinline__ ull pk2(float lo, float hi) {
    ull r; asm("mov.b64 %0, {%1, %2};" : "=l"(r) : "f"(lo), "f"(hi)); return r;
}
__device__ __forceinline__ void upk2(ull v, float& lo, float& hi) {
    asm("mov.b64 {%0, %1}, %2;" : "=f"(lo), "=f"(hi) : "l"(v));
}
__device__ __forceinline__ ull fma2(ull a, ull b, ull c) {
    ull d; asm("fma.rn.f32x2 %0, %1, %2, %3;" : "=l"(d) : "l"(a), "l"(b), "l"(c));
    return d;
}

// Branchless gelu: Abramowitz-Stegun 7.1.26 erf approx (|abs err| < 1.5e-7)
__device__ __forceinline__ float gelu_f(float x) {
    float z = 0.7071067811865476f * x;
    float s = fabsf(z);
    float t = __fdividef(1.0f, fmaf(0.3275911f, s, 1.0f));
    float p = fmaf(fmaf(fmaf(fmaf(1.061405429f, t, -1.453152027f),
                             t, 1.421413741f), t, -0.284496736f), t, 0.254829592f) * t;
    float e = __expf(-s * s);
    float er = fmaf(-p, e, 1.0f);
    er = copysignf(er, z);
    return 0.5f * x * (1.0f + er);
}

// ---------------------------------------------------------------------------
// First conv (per-half): wrap-pad (25,27), conv3 10->20.
// ---------------------------------------------------------------------------
__global__ void __launch_bounds__(128) k_first(
    const float* __restrict__ in, const float* __restrict__ w,
    float* __restrict__ out, int lout, int b0)
{
    __shared__ float sw[CH_ * INC_ * 3];
    int tid = threadIdx.x;
    for (int i = tid; i < CH_ * INC_ * 3; i += blockDim.x) sw[i] = w[i];
    __syncthreads();

    int b = b0 + blockIdx.y;
    int t = blockIdx.x * blockDim.x + tid;
    if (t >= lout) return;

    int base = t - 25;
    int i0 = base;     if (i0 < 0) i0 += LIN_; else if (i0 >= LIN_) i0 -= LIN_;
    int i1 = base + 1; if (i1 < 0) i1 += LIN_; else if (i1 >= LIN_) i1 -= LIN_;
    int i2 = base + 2; if (i2 < 0) i2 += LIN_; else if (i2 >= LIN_) i2 -= LIN_;

    const float* inb = in + (size_t)b * INC_ * LIN_;
    float acc[CH_];
#pragma unroll
    for (int co = 0; co < CH_; co++) acc[co] = 0.f;
#pragma unroll
    for (int ci = 0; ci < INC_; ci++) {
        float v0 = inb[ci * LIN_ + i0];
        float v1 = inb[ci * LIN_ + i1];
        float v2 = inb[ci * LIN_ + i2];
#pragma unroll
        for (int co = 0; co < CH_; co++) {
            const float* wp = sw + (co * INC_ + ci) * 3;
            acc[co] = fmaf(wp[0], v0, fmaf(wp[1], v1, fmaf(wp[2], v2, acc[co])));
        }
    }
    float* ob = out + (size_t)b * CH_ * lout;
#pragma unroll
    for (int co = 0; co < CH_; co++) ob[co * lout + t] = acc[co];
}

// ---------------------------------------------------------------------------
// conv3 20->20, VALID, VT=2, direct LDG. lout always even -> both positions
// always valid when t0 < lout (has2 branch eliminated).
// ---------------------------------------------------------------------------
template <bool DO_GELU>
__global__ void __launch_bounds__(128) k_conv20(
    const float* __restrict__ x, const float* __restrict__ w,
    float* __restrict__ out, int lin, int b0)
{
    __shared__ float sw[CH_ * CH_ * 3];
    int tid = threadIdx.x;
    for (int i = tid; i < CH_ * CH_ * 3; i += blockDim.x) sw[i] = w[i];
    __syncthreads();

    int lout = lin - 2;   // even
    int b = b0 + blockIdx.y;
    int t0 = (blockIdx.x * blockDim.x + tid) * 2;
    if (t0 >= lout) return;

    const float* xb = x + (size_t)b * CH_ * lin;
    float a0[CH_], a1[CH_];
#pragma unroll
    for (int co = 0; co < CH_; co++) { a0[co] = 0.f; a1[co] = 0.f; }

#pragma unroll
    for (int ci = 0; ci < CH_; ci++) {
        const float* xp = xb + ci * lin + t0;
        float v0 = xp[0], v1 = xp[1], v2 = xp[2], v3 = xp[3];
#pragma unroll
        for (int co = 0; co < CH_; co++) {
            const float* wp = sw + (co * CH_ + ci) * 3;
            float w0 = wp[0], w1 = wp[1], w2 = wp[2];
            a0[co] = fmaf(w0, v0, fmaf(w1, v1, fmaf(w2, v2, a0[co])));
            a1[co] = fmaf(w0, v1, fmaf(w1, v2, fmaf(w2, v3, a1[co])));
        }
    }
    float* ob = out + (size_t)b * CH_ * lout;
#pragma unroll
    for (int co = 0; co < CH_; co++) {
        float u0 = a0[co], u1 = a1[co];
        if (DO_GELU) { u0 = gelu_f(u0); u1 = gelu_f(u1); }
        ob[co * lout + t0] = u0;
        ob[co * lout + t0 + 1] = u1;
    }
}

// ---------------------------------------------------------------------------
// Legendre decomposition + cross-channel block-diag mixing (R2 version,
// 640 threads, measured 62us/full-batch, regs=38). b0 = batch offset.
// ---------------------------------------------------------------------------
#define TB_ 32
__global__ void __launch_bounds__(640) k_legmix(
    const float* __restrict__ x, const float* __restrict__ lm_g,
    const float* __restrict__ fd, float* __restrict__ Lg,
    int lin, int ll, int b0)
{
    __shared__ float xs[CH_][TB_ * 6 + 6];   // 20 x 198
    __shared__ float fd2[MM_ * NPOLY];
    __shared__ float lm[CH_ * MM_ * MM_];

    int b = b0 + blockIdx.y;
    int T0 = blockIdx.x * TB_;
    int tid = threadIdx.y * TB_ + threadIdx.x;

    for (int i = tid; i < MM_ * NPOLY; i += 640) fd2[i] = 0.5f * fd[i];
    for (int i = tid; i < CH_ * MM_ * MM_; i += 640) lm[i] = lm_g[i];
    for (int i = tid; i < CH_ * (TB_ * 6 + 6); i += 640) {
        int ci = i / (TB_ * 6 + 6);
        int j  = i % (TB_ * 6 + 6);
        int pos = 6 * T0 + j;
        xs[ci][j] = (pos < lin) ? x[((size_t)b * CH_ + ci) * lin + pos] : 0.f;
    }
    __syncthreads();

    int tloc = threadIdx.x;
    int g = threadIdx.y;
    int t = T0 + tloc;
    if (t >= ll) return;

    float v[MM_];
#pragma unroll
    for (int i = 0; i < MM_; i++) {
        int q  = 6 * g + i;
        int mi = q / CH_;
        int ci = q % CH_;
        float s = 0.f;
#pragma unroll
        for (int k = 0; k < NPOLY; k++)
            s = fmaf(fd2[mi * NPOLY + k], xs[ci][6 * tloc + k], s);
        v[i] = s;
    }
#pragma unroll
    for (int o = 0; o < MM_; o++) {
        float s = 0.f;
#pragma unroll
        for (int i = 0; i < MM_; i++)
            s = fmaf(lm[(g * MM_ + o) * MM_ + i], v[i], s);
        int p  = 6 * g + o;
        int mo = p / CH_;
        int co = p % CH_;
        Lg[(((size_t)b * MM_ + mo) * CH_ + co) * ll + t] = s;
    }
}

// ---------------------------------------------------------------------------
// Overlap-add reconstruction + residual + gelu, VT=6. b0 = batch offset.
// blockIdx.y spans HB_*CH_.
// ---------------------------------------------------------------------------
__global__ void __launch_bounds__(128) k_recon(
    const float* __restrict__ Lg, const float* __restrict__ fr,
    const float* __restrict__ y2, float* __restrict__ out,
    int ll, int lout, int b0)
{
    __shared__ float sfr[MM_ * NPOLY];
    __shared__ float sbuf[128 * 6];

    int tid = threadIdx.x;
    if (tid < MM_ * NPOLY) sfr[tid] = fr[tid];
    __syncthreads();

    int bc = b0 * CH_ + blockIdx.y;
    int b = bc / CH_, co = bc % CH_;
    int nu = lout / 6;

    int u = blockIdx.x * 128 + tid;
    if (u < nu) {
        int t0 = u + 1;
        const float* Lo = Lg + (((size_t)b * MM_) * CH_ + co) * ll;
        size_t mstride = (size_t)CH_ * ll;
        float rec[6];
#pragma unroll
        for (int e = 0; e < 6; e++) rec[e] = 0.f;
#pragma unroll
        for (int m = 0; m < MM_; m++) {
            float uc = Lo[m * mstride + t0];
            float up = Lo[m * mstride + t0 - 1];
#pragma unroll
            for (int e = 0; e < 6; e++) {
                rec[e] = fmaf(uc, sfr[m * NPOLY + e],     rec[e]);
                rec[e] = fmaf(up, sfr[m * NPOLY + e + 6], rec[e]);
            }
        }
#pragma unroll
        for (int e = 0; e < 6; e++) sbuf[6 * tid + e] = rec[e];
    }
    __syncthreads();

    int Tbase = blockIdx.x * 768;
    int liny2 = lout + 8;
    const float* y2r = y2 + (size_t)bc * liny2;
    float* outr = out + (size_t)bc * lout;
#pragma unroll
    for (int e2 = 0; e2 < 6; e2++) {
        int idx = tid + 128 * e2;
        int t = Tbase + idx;
        if (t < lout)
            outr[t] = gelu_f(sbuf[idx] + y2r[t + 4]);
    }
}

// ---------------------------------------------------------------------------
// Final 20->128(gelu)->1 with f32x2, VT=4 (per-half).
// ---------------------------------------------------------------------------
__global__ void __launch_bounds__(128) k_final_f2(
    const float* __restrict__ x, const float* __restrict__ w11,
    const float* __restrict__ w_out, float* __restrict__ out, int lin, int b0)
{
    __shared__ __align__(16) float2 swd[128 * CH_];
    __shared__ float so[128];
    int tid = threadIdx.x;
    for (int i = tid; i < 128 * CH_; i += 128) {
        float v = w11[i];
        swd[i] = make_float2(v, v);
    }
    if (tid < 128) so[tid] = w_out[tid];
    __syncthreads();

    int b = b0 + blockIdx.y;
    int t0 = (blockIdx.x * 128 + tid) * 4;
    if (t0 >= LIN_) return;

    const float* xb = x + (size_t)b * CH_ * lin + t0;
    ull xv01[CH_], xv23[CH_];
#pragma unroll
    for (int c = 0; c < CH_; c++) {
        const float* xp = xb + c * lin;
        xv01[c] = pk2(xp[0], xp[1]);
        xv23[c] = pk2(xp[2], xp[3]);
    }

    ull zero = pk2(0.f, 0.f);
    ull acc01 = zero, acc23 = zero;
#pragma unroll 2
    for (int o = 0; o < 128; o++) {
        ull h01 = zero, h23 = zero;
#pragma unroll
        for (int c = 0; c < CH_; c++) {
            ull wv = *(const ull*)&swd[o * CH_ + c];
            h01 = fma2(wv, xv01[c], h01);
            h23 = fma2(wv, xv23[c], h23);
        }
        float h0, h1, h2, h3;
        upk2(h01, h0, h1); upk2(h23, h2, h3);
        float ov = so[o];
        ull ov2 = pk2(ov, ov);
        acc01 = fma2(ov2, pk2(gelu_f(h0), gelu_f(h1)), acc01);
        acc23 = fma2(ov2, pk2(gelu_f(h2), gelu_f(h3)), acc23);
    }
    float r0, r1, r2, r3;
    upk2(acc01, r0, r1); upk2(acc23, r2, r3);
    float4* op = (float4*)&out[(size_t)b * LIN_ + t0];
    *op = make_float4(r0, r1, r2, r3);
}

// ---------------------------------------------------------------------------
extern "C" void kernel_launch(void* const* d_in, const int* in_sizes, int n_in,
                              void* d_out, int out_size)
{
    const float* input  = (const float*)d_in[0];
    const float* w_first= (const float*)d_in[1];
    const float* conv_a = (const float*)d_in[2];
    const float* conv_b = (const float*)d_in[3];
    const float* lin_m  = (const float*)d_in[4];
    const float* w11    = (const float*)d_in[5];
    const float* w_out  = (const float*)d_in[6];
    const float* filt_d = (const float*)d_in[7];
    const float* filt_r = (const float*)d_in[8];
    float* out = (float*)d_out;

    float *xa, *xb, *y1, *y2, *Lg;
    cudaGetSymbolAddress((void**)&xa, g_xa);
    cudaGetSymbolAddress((void**)&xb, g_xb);
    cudaGetSymbolAddress((void**)&y1, g_y1);
    cudaGetSymbolAddress((void**)&y2, g_y2);
    cudaGetSymbolAddress((void**)&Lg, g_lg);

    // Per-iteration lengths and ping-pong buffers
    int lA[NB_], llA[NB_], loA[NB_];
    float* curA[NB_ + 1];
    curA[0] = xa;
    {
        int l = 16434;
        for (int i = 0; i < NB_; i++) {
            lA[i] = l; llA[i] = l / 6 - 1; loA[i] = l - 12;
            curA[i + 1] = (i % 2 == 0) ? xb : xa;
            l -= 12;
        }
    }

    // Fork-join resources — same footprint as R14/R16 (capture-safe).
    cudaStream_t s1;
    cudaStreamCreateWithFlags(&s1, cudaStreamNonBlocking);
    cudaEvent_t evRoot, evA[NB_], evJ;
    cudaEventCreateWithFlags(&evRoot, cudaEventDisableTiming);
    for (int i = 0; i < NB_; i++)
        cudaEventCreateWithFlags(&evA[i], cudaEventDisableTiming);
    cudaEventCreateWithFlags(&evJ, cudaEventDisableTiming);

    auto launchFirst = [&](int h, cudaStream_t s) {
        dim3 g((16434 + 127) / 128, HB_);
        k_first<<<g, 128, 0, s>>>(input, w_first, xa, 16434, h * HB_);
    };
    auto launchL = [&](int i, int h, cudaStream_t s) {
        dim3 g((llA[i] + TB_ - 1) / TB_, HB_);
        k_legmix<<<g, dim3(TB_, CH_), 0, s>>>(curA[i], lin_m + i * 720,
                                              filt_d, Lg, lA[i], llA[i], h * HB_);
    };
    auto launchA = [&](int i, int h, cudaStream_t s) {
        dim3 g((lA[i] - 2 + 255) / 256, HB_);
        k_conv20<true><<<g, 128, 0, s>>>(curA[i], conv_a + i * 1200,
                                         y1, lA[i], h * HB_);
    };
    auto launchC = [&](int i, int h, cudaStream_t s) {
        int l1 = lA[i] - 2;
        dim3 g((l1 - 2 + 255) / 256, HB_);
        k_conv20<false><<<g, 128, 0, s>>>(y1, conv_b + i * 1200,
                                          y2, l1, h * HB_);
    };
    auto launchR = [&](int i, int h, cudaStream_t s) {
        dim3 g((loA[i] / 6 + 127) / 128, HB_ * CH_);
        k_recon<<<g, 128, 0, s>>>(Lg, filt_r, y2, curA[i + 1],
                                  llA[i], loA[i], h * HB_);
    };
    auto launchFinal = [&](int h, cudaStream_t s) {
        dim3 g((LIN_ / 4 + 127) / 128, HB_);
        k_final_f2<<<g, 128, 0, s>>>(curA[NB_], w11, w_out, out,
                                     loA[NB_ - 1], h * HB_);
    };

    // Fork: root event on capture-origin stream.
    cudaEventRecord(evRoot, 0);

    // Stream 0: h0 chain. Per iter: L, A, (event), C, R.
    launchFirst(0, 0);
    for (int i = 0; i < NB_; i++) {
        launchL(i, 0, 0);
        launchA(i, 0, 0);
        cudaEventRecord(evA[i], 0);
        launchC(i, 0, 0);
        launchR(i, 0, 0);
    }
    launchFinal(0, 0);

    // Stream 1: h1 chain, per-iter skew on s0's A event.
    cudaStreamWaitEvent(s1, evRoot, 0);
    launchFirst(1, s1);
    for (int i = 0; i < NB_; i++) {
        cudaStreamWaitEvent(s1, evA[i], 0);
        launchL(i, 1, s1);
        launchA(i, 1, s1);
        launchC(i, 1, s1);
        launchR(i, 1, s1);
    }
    launchFinal(1, s1);

    // Join s1 back into the capture-origin stream.
    cudaEventRecord(evJ, s1);
    cudaStreamWaitEvent(0, evJ, 0);
}